// round 15
// baseline (speedup 1.0000x reference)
#include <cuda_runtime.h>
#include <cuda_fp16.h>
#include <math.h>
#include <stdint.h>

// ---------------- problem constants ----------------
#define BB   8
#define C0   512
#define HW0  64
#define N0   64
#define L0   8
#define KN0  4
#define C1   64
#define HW1  16384
#define N1   512
#define L1   80
#define KN1  40
#define M1   41
#define NS0  (BB*N0)     // 512
#define NS1  (BB*N1)     // 4096
#define ROWS1 (NS1*M1)   // 167936
#define H1   1024
#define O0   256
#define O1   256
#define NT2  (ROWS1/64)  // 2624 tiles of 64 rows
#define MGRID 264        // 2 CTAs x 132 SMs; 16 SMs left for branch B

// ---------------- scratch ----------------
__device__ float  g_fr0[BB*HW0*C0];
__device__ float  g_fr1[BB*HW1*C1];
__device__ float  g_H [NS0*H1];
__device__ float  g_scale[H1];
__device__ float  g_shift[H1];
__device__ float  g_bnp[2*4*H1];
__device__ __half g_X0h[NS0*C0];
__device__ __half g_Ah [NS0*H1];
__device__ __half g_W1h[H1*C0];
__device__ __half g_W2h[O0*H1];
__device__ __half g_W3h[256*64];
__device__ __half g_W4h[256*256];
__device__ __half g_X1h[(long)ROWS1*C1];

// ---------------- fp16 mma helpers ----------------
__device__ __forceinline__ int reord16(int k) { return ((k & 7) >> 1) * 4 + ((k >> 3) & 1) * 2 + (k & 1); }
__device__ __forceinline__ int reordk(int k)  { return (k & ~15) + reord16(k & 15); }

__device__ __forceinline__ void mma16(float acc[4], uint32_t a0, uint32_t a1,
                                      uint32_t a2, uint32_t a3, uint32_t b0, uint32_t b1) {
    asm volatile(
        "mma.sync.aligned.m16n8k16.row.col.f32.f16.f16.f32 "
        "{%0,%1,%2,%3}, {%4,%5,%6,%7}, {%8,%9}, {%0,%1,%2,%3};"
        : "+f"(acc[0]), "+f"(acc[1]), "+f"(acc[2]), "+f"(acc[3])
        : "r"(a0), "r"(a1), "r"(a2), "r"(a3), "r"(b0), "r"(b1));
}
__device__ __forceinline__ uint32_t pack2(float a, float b) {
    __half2 h = __floats2half2_rn(a, b);
    return *(uint32_t*)&h;
}
__device__ __forceinline__ void cp8(uint32_t dst, const void* src) {
    asm volatile("cp.async.ca.shared.global [%0], [%1], 8;" :: "r"(dst), "l"(src));
}
#define CP_COMMIT() asm volatile("cp.async.commit_group;" ::: "memory")
#define CP_WAIT0()  asm volatile("cp.async.wait_group 0;" ::: "memory")

// ---------------- split weight conversions (per branch) ----------------
__global__ void cvt12(const float* __restrict__ W1, const float* __restrict__ W2) {
    long i = (long)blockIdx.x * blockDim.x + threadIdx.x;   // 786432
    const float* src; __half* dst; long base; int mask;
    if (i < 524288L) { src = W1; dst = g_W1h; base = 0;       mask = 511; }
    else             { src = W2; dst = g_W2h; base = 524288L; mask = 1023; }
    long j = i - base;
    int k = (int)j & mask;
    dst[j - k + reordk(k)] = __float2half_rn(src[j]);
}
__global__ void cvt34(const float* __restrict__ W3, const float* __restrict__ W4) {
    long i = (long)blockIdx.x * blockDim.x + threadIdx.x;   // 81920
    const float* src; __half* dst; long base; int mask;
    if (i < 16384L) { src = W3; dst = g_W3h; base = 0;      mask = 63; }
    else            { src = W4; dst = g_W4h; base = 16384L; mask = 255; }
    long j = i - base;
    int k = (int)j & mask;
    dst[j - k + reordk(k)] = __float2half_rn(src[j]);
}

// ---------------- coalesced transposes ----------------
__global__ void transpose_feat1(const float* __restrict__ f, float* __restrict__ out) {
    __shared__ float sm[64 * 33];
    int b = blockIdx.y;
    int p0 = blockIdx.x * 32;
    int t = threadIdx.x;
    int pp = t & 31, c0 = t >> 5;
    #pragma unroll
    for (int i = 0; i < 8; i++) {
        int c = c0 + i * 8;
        sm[c * 33 + pp] = f[((long)b * 64 + c) * 16384 + p0 + pp];
    }
    __syncthreads();
    #pragma unroll
    for (int i = 0; i < 8; i++) {
        int idx = i * 256 + t;
        int p = idx >> 6, c = idx & 63;
        out[((long)b * 16384 + p0 + p) * 64 + c] = sm[c * 33 + p];
    }
}
__global__ void transpose_feat0(const float* __restrict__ f, float* __restrict__ out) {
    __shared__ float sm[32 * 65];
    int b = blockIdx.y;
    int c0 = blockIdx.x * 32;
    int t = threadIdx.x;
    int p = t & 63, cc = t >> 6;
    #pragma unroll
    for (int i = 0; i < 8; i++) {
        int c = cc + i * 4;
        sm[c * 65 + p] = f[((long)b * 512 + c0 + c) * 64 + p];
    }
    __syncthreads();
    #pragma unroll
    for (int i = 0; i < 8; i++) {
        int idx = i * 256 + t;
        int p2 = idx >> 5, c = idx & 31;
        out[((long)b * 64 + p2) * 512 + c0 + c] = sm[c * 65 + p2];
    }
}

// ---------------- path0 sampling ----------------
__global__ void sample0_kernel(const int* __restrict__ pid, const int* __restrict__ lid) {
    __shared__ float cen[C0];
    __shared__ float sim[L0];
    __shared__ int   rowsS[L0];
    __shared__ int   chosen[KN0];
    int blk = blockIdx.x;
    int b = blk / N0, n = blk % N0;
    int t = threadIdx.x;
    int p = pid[n];
    const float* base = g_fr0 + (long)b * HW0 * C0;
    const float* cptr = base + (long)p * C0;
    for (int c = t; c < C0; c += 256) cen[c] = cptr[c];
    if (t < L0) rowsS[t] = lid[n * L0 + t];
    __syncthreads();
    int w = t >> 5, lane = t & 31;
    {
        const float* lp = base + (long)rowsS[w] * C0;
        float dot = 0.f, ss = 0.f;
        for (int c = lane; c < C0; c += 32) {
            float v = lp[c];
            dot += v * cen[c];
            ss  += v * v;
        }
        for (int o = 16; o > 0; o >>= 1) {
            dot += __shfl_down_sync(0xffffffffu, dot, o);
            ss  += __shfl_down_sync(0xffffffffu, ss,  o);
        }
        if (lane == 0) sim[w] = dot / fmaxf(sqrtf(ss), 1e-12f);
    }
    __syncthreads();
    if (t < L0) {
        int l = t;
        float v = sim[l];
        int cnt = 0;
        #pragma unroll
        for (int j = 0; j < L0; j++) {
            float u = sim[j];
            cnt += (u > v || (u == v && j < l)) ? 1 : 0;
        }
        if (cnt < KN0) chosen[cnt] = rowsS[l];
    }
    __syncthreads();
    for (int c = t; c < C0; c += 256) {
        float acc = cen[c];
        #pragma unroll
        for (int r = 0; r < KN0; r++) acc += base[(long)chosen[r] * C0 + c];
        g_X0h[(long)blk * C0 + reordk(c)] = __float2half_rn(acc * 0.2f);
    }
}

// ---------------- path1 sampling ----------------
__global__ void sample1_kernel(const int* __restrict__ pid, const int* __restrict__ lid) {
    __shared__ float cen[C1];
    __shared__ float loc[L1 * 68];
    __shared__ float sim[L1];
    __shared__ int   rowsS[L1];
    __shared__ int   sel[KN1];
    int blk = blockIdx.x;
    int b = blk / N1, n = blk % N1;
    int t = threadIdx.x;
    const float* base = g_fr1 + (long)b * HW1 * C1;
    int p = pid[n];
    if (t < C1) cen[t] = base[(long)p * C1 + t];
    if (t < L1) rowsS[t] = lid[n * L1 + t];
    __syncthreads();
    #pragma unroll
    for (int i = t; i < L1 * 16; i += 256) {
        int l = i >> 4, c4 = i & 15;
        float4 v = *(const float4*)(base + (long)rowsS[l] * C1 + c4 * 4);
        *(float4*)(loc + l * 68 + c4 * 4) = v;
    }
    __syncthreads();
    if (t < L1) {
        const float4* lp = (const float4*)(loc + t * 68);
        const float4* cp = (const float4*)cen;
        float dot = 0.f, ss = 0.f;
        #pragma unroll
        for (int c4 = 0; c4 < 16; c4++) {
            float4 v = lp[c4], cv = cp[c4];
            dot += v.x * cv.x + v.y * cv.y + v.z * cv.z + v.w * cv.w;
            ss  += v.x * v.x + v.y * v.y + v.z * v.z + v.w * v.w;
        }
        sim[t] = dot / fmaxf(sqrtf(ss), 1e-12f);
    }
    __syncthreads();
    if (t < L1) {
        int l = t;
        float v = sim[l];
        int cnt = 0;
        #pragma unroll
        for (int j = 0; j < L1; j++) {
            float u = sim[j];
            cnt += (u > v || (u == v && j < l)) ? 1 : 0;
        }
        if (cnt < KN1) sel[cnt] = l;
    }
    __syncthreads();
    uint2* outp = (uint2*)(g_X1h + (long)blk * M1 * C1);
    #pragma unroll
    for (int i = t; i < M1 * 16; i += 256) {
        int m = i >> 4, q = i & 15;
        int b16 = q >> 2, tq = q & 3;
        int c0 = 16 * b16 + 2 * tq;
        const float* srcp = (m == 0) ? cen : (loc + sel[m - 1] * 68);
        uint2 o;
        o.x = pack2(srcp[c0], srcp[c0 + 1]);
        o.y = pack2(srcp[c0 + 8], srcp[c0 + 9]);
        outp[m * 16 + q] = o;
    }
}

// ---------------- fp16 mma GEMM (path0); optional BN-partial epilogue ----------------
template<int BNSTATS>
__global__ __launch_bounds__(256) void gemm_fp16(const __half* __restrict__ Ah,
                                                 const __half* __restrict__ Bh,
                                                 const float* __restrict__ bias,
                                                 float* __restrict__ C,
                                                 int M, int N, int K) {
    __shared__ __half sA[128 * 48];
    __shared__ __half sB[64 * 48];
    int t = threadIdx.x;
    int w = t >> 5, lane = t & 31;
    int g = lane >> 2, tg = lane & 3;
    int rw0 = w * 16;
    int m0 = blockIdx.y * 128, n0 = blockIdx.x * 64;

    float acc[8][4];
    #pragma unroll
    for (int nt = 0; nt < 8; nt++)
        #pragma unroll
        for (int q = 0; q < 4; q++) acc[nt][q] = 0.f;

    for (int kc = 0; kc < K / 32; kc++) {
        __syncthreads();
        #pragma unroll
        for (int i = 0; i < 2; i++) {
            int idx = i * 256 + t;
            int r = idx >> 2, q = idx & 3;
            *(uint4*)(sA + r * 48 + q * 8) =
                *(const uint4*)(Ah + (long)(m0 + r) * K + kc * 32 + q * 8);
        }
        {
            int r = t >> 2, q = t & 3;
            *(uint4*)(sB + r * 48 + q * 8) =
                *(const uint4*)(Bh + (long)(n0 + r) * K + kc * 32 + q * 8);
        }
        __syncthreads();
        #pragma unroll
        for (int ks = 0; ks < 2; ks++) {
            uint2 alo = *(const uint2*)(sA + (rw0 + g) * 48 + ks * 16 + 4 * tg);
            uint2 ahi = *(const uint2*)(sA + (rw0 + g + 8) * 48 + ks * 16 + 4 * tg);
            #pragma unroll
            for (int nt = 0; nt < 8; nt++) {
                uint2 bb = *(const uint2*)(sB + (nt * 8 + g) * 48 + ks * 16 + 4 * tg);
                mma16(acc[nt], alo.x, ahi.x, alo.y, ahi.y, bb.x, bb.y);
            }
        }
    }
    __shared__ float red[2][8][64];
    #pragma unroll
    for (int nt = 0; nt < 8; nt++) {
        int col = n0 + nt * 8 + 2 * tg;
        float bj0 = bias[col], bj1 = bias[col + 1];
        float y00 = acc[nt][0] + bj0, y01 = acc[nt][1] + bj1;
        float y10 = acc[nt][2] + bj0, y11 = acc[nt][3] + bj1;
        C[(long)(m0 + rw0 + g    ) * N + col    ] = y00;
        C[(long)(m0 + rw0 + g    ) * N + col + 1] = y01;
        C[(long)(m0 + rw0 + g + 8) * N + col    ] = y10;
        C[(long)(m0 + rw0 + g + 8) * N + col + 1] = y11;
        if (BNSTATS) {
            float s0 = y00 + y10, q0 = y00 * y00 + y10 * y10;
            float s1 = y01 + y11, q1 = y01 * y01 + y11 * y11;
            #pragma unroll
            for (int o = 16; o >= 4; o >>= 1) {
                s0 += __shfl_down_sync(0xffffffffu, s0, o);
                q0 += __shfl_down_sync(0xffffffffu, q0, o);
                s1 += __shfl_down_sync(0xffffffffu, s1, o);
                q1 += __shfl_down_sync(0xffffffffu, q1, o);
            }
            if (g == 0) {
                red[0][w][nt * 8 + 2 * tg]     = s0;
                red[0][w][nt * 8 + 2 * tg + 1] = s1;
                red[1][w][nt * 8 + 2 * tg]     = q0;
                red[1][w][nt * 8 + 2 * tg + 1] = q1;
            }
        }
    }
    if (BNSTATS) {
        __syncthreads();
        if (t < 64) {
            float s = 0.f, q = 0.f;
            #pragma unroll
            for (int ww = 0; ww < 8; ww++) { s += red[0][ww][t]; q += red[1][ww][t]; }
            g_bnp[blockIdx.y * H1 + n0 + t] = s;
            g_bnp[4 * H1 + blockIdx.y * H1 + n0 + t] = q;
        }
    }
}

// ---------------- BN finish ----------------
__global__ void bnstatsB_kernel(const float* __restrict__ gamma, const float* __restrict__ beta) {
    int j = blockIdx.x * 256 + threadIdx.x;
    float s = 0.f, ss = 0.f;
    #pragma unroll
    for (int b = 0; b < 4; b++) {
        s  += g_bnp[b * H1 + j];
        ss += g_bnp[4 * H1 + b * H1 + j];
    }
    float mu  = s / NS0;
    float var = ss / NS0 - mu * mu;
    float sc  = gamma[j] / sqrtf(var + 1e-5f);
    g_scale[j] = sc;
    g_shift[j] = beta[j] - mu * sc;
}
__global__ void bnapply_kernel() {
    long total = (long)NS0 * H1;
    for (long i = (long)blockIdx.x * blockDim.x + threadIdx.x; i < total;
         i += (long)gridDim.x * blockDim.x) {
        int j = (int)(i % H1);
        float v = g_H[i] * g_scale[j] + g_shift[j];
        g_Ah[i - j + reordk(j)] = __float2half_rn(fmaxf(v, 0.f));
    }
}

// ================= path1 MLP: 64-row tiles, 2 CTAs/SM, W3/W4 frags via L1 ==========
#define X2_OFF  0u
#define H2_OFF  8192u
#define FB2_OFF 40960u
#define MLP_SMEM_BYTES (40960 + 832*4)

__global__ __launch_bounds__(256, 2) void mlp_fp16_kernel(const float* __restrict__ b3,
                                                          const float* __restrict__ b4,
                                                          float* __restrict__ out1) {
    extern __shared__ char sm[];
    float* sb3   = (float*)(sm + FB2_OFF);
    float* sb4   = sb3 + 256;
    float* spart = sb4 + 256;   // [64][4]
    float* srn   = spart + 256; // [64]

    int t = threadIdx.x;
    int lane = t & 31;
    int g = lane >> 2, tg = lane & 3;
    int w = t >> 5;
    int wm = w >> 2;            // 0..1 (rows 32*wm)
    int wn = w & 3;             // 0..3 (cols 64*wn)
    int bid = blockIdx.x;

    uint32_t sbase = (uint32_t)__cvta_generic_to_shared(sm);

    // X tile0 fragments (64 rows x 64 k = 1024 x 8B)
    {
        long tile0 = bid;
        #pragma unroll 4
        for (int i = t; i < 1024; i += 256) {
            int f = i >> 6, rest = i & 63;
            int l = rest >> 1, h = rest & 1;
            int mb = f >> 2, ks = f & 3, gg = l >> 2, tt = l & 3;
            cp8(sbase + X2_OFF + (uint32_t)(f * 512 + l * 16 + h * 8),
                g_X1h + (tile0 * 64 + 16 * mb + gg + 8 * h) * 64 + 16 * ks + 4 * tt);
        }
    }
    CP_COMMIT();
    sb3[t] = b3[t];
    sb4[t] = b4[t];
    CP_WAIT0();
    __syncthreads();

    const uint2* W3f = (const uint2*)g_W3h;
    const uint2* W4f = (const uint2*)g_W4h;

    for (long tile = bid; tile < NT2; tile += MGRID) {
        long row0 = tile * 64;

        // ---- stage 1: H = relu(X @ W3^T + b3); warp tile 32 rows x 64 cols ----
        float acc1[2][8][4];
        #pragma unroll
        for (int mt = 0; mt < 2; mt++)
            #pragma unroll
            for (int nt = 0; nt < 8; nt++)
                #pragma unroll
                for (int q = 0; q < 4; q++) acc1[mt][nt][q] = 0.f;

        #pragma unroll
        for (int ks = 0; ks < 4; ks++) {
            uint4 ax[2];
            #pragma unroll
            for (int mt = 0; mt < 2; mt++)
                ax[mt] = *(const uint4*)(sm + X2_OFF + ((2 * wm + mt) * 4 + ks) * 512 + lane * 16);
            #pragma unroll
            for (int nt = 0; nt < 8; nt++) {
                uint2 bb = __ldg(W3f + (((8 * wn + nt) * 8 + g) * 64 + 16 * ks + 4 * tg) / 4);
                #pragma unroll
                for (int mt = 0; mt < 2; mt++)
                    mma16(acc1[mt][nt], ax[mt].x, ax[mt].z, ax[mt].y, ax[mt].w, bb.x, bb.y);
            }
        }
        #pragma unroll
        for (int mt = 0; mt < 2; mt++)
            #pragma unroll
            for (int nt = 0; nt < 8; nt++) {
                int c = 64 * wn + 8 * nt + 2 * tg;
                float bb0 = sb3[c], bb1 = sb3[c + 1];
                uint2 v;
                v.x = pack2(fmaxf(acc1[mt][nt][0] + bb0, 0.f), fmaxf(acc1[mt][nt][1] + bb1, 0.f));
                v.y = pack2(fmaxf(acc1[mt][nt][2] + bb0, 0.f), fmaxf(acc1[mt][nt][3] + bb1, 0.f));
                int mb = 2 * wm + mt;
                int ck = 4 * wn + (nt >> 1);
                *(uint2*)(sm + H2_OFF + (mb * 16 + ck) * 512 + lane * 16 + (nt & 1) * 8) = v;
            }
        __syncthreads();   // H visible; X consumed

        // ---- prefetch next X tile (overlaps stage 2) ----
        {
            long tn = tile + MGRID;
            if (tn < NT2) {
                #pragma unroll 4
                for (int i = t; i < 1024; i += 256) {
                    int f = i >> 6, rest = i & 63;
                    int l = rest >> 1, h = rest & 1;
                    int mb = f >> 2, ks = f & 3, gg = l >> 2, tt = l & 3;
                    cp8(sbase + X2_OFF + (uint32_t)(f * 512 + l * 16 + h * 8),
                        g_X1h + (tn * 64 + 16 * mb + gg + 8 * h) * 64 + 16 * ks + 4 * tt);
                }
            }
            CP_COMMIT();
        }

        // ---- stage 2: Y = H @ W4^T; warp tile 32 rows x 64 cols; W4 frags via L1 ----
        float acc2[2][8][4];
        #pragma unroll
        for (int mt = 0; mt < 2; mt++)
            #pragma unroll
            for (int nt = 0; nt < 8; nt++)
                #pragma unroll
                for (int q = 0; q < 4; q++) acc2[mt][nt][q] = 0.f;

        #pragma unroll 4
        for (int ck = 0; ck < 16; ck++) {
            uint4 ha[2];
            #pragma unroll
            for (int mt = 0; mt < 2; mt++)
                ha[mt] = *(const uint4*)(sm + H2_OFF + ((2 * wm + mt) * 16 + ck) * 512 + lane * 16);
            uint2 wb[8];
            #pragma unroll
            for (int nt = 0; nt < 8; nt++)
                wb[nt] = __ldg(W4f + (((8 * wn + nt) * 8 + g) * 256 + 16 * ck + 4 * tg) / 4);
            #pragma unroll
            for (int nt = 0; nt < 8; nt++)
                #pragma unroll
                for (int mt = 0; mt < 2; mt++)
                    mma16(acc2[mt][nt], ha[mt].x, ha[mt].y, ha[mt].z, ha[mt].w,
                          wb[nt].x, wb[nt].y);
        }

        // ---- epilogue: +b4, cross-warp row sumsq, L2 norm, store ----
        float slo[2] = {0.f, 0.f}, shi[2] = {0.f, 0.f};
        #pragma unroll
        for (int mt = 0; mt < 2; mt++)
            #pragma unroll
            for (int nt = 0; nt < 8; nt++) {
                int c = 64 * wn + 8 * nt + 2 * tg;
                float bb0 = sb4[c], bb1 = sb4[c + 1];
                acc2[mt][nt][0] += bb0; acc2[mt][nt][1] += bb1;
                acc2[mt][nt][2] += bb0; acc2[mt][nt][3] += bb1;
                slo[mt] += acc2[mt][nt][0] * acc2[mt][nt][0] + acc2[mt][nt][1] * acc2[mt][nt][1];
                shi[mt] += acc2[mt][nt][2] * acc2[mt][nt][2] + acc2[mt][nt][3] * acc2[mt][nt][3];
            }
        #pragma unroll
        for (int mt = 0; mt < 2; mt++) {
            slo[mt] += __shfl_xor_sync(0xffffffffu, slo[mt], 1);
            slo[mt] += __shfl_xor_sync(0xffffffffu, slo[mt], 2);
            shi[mt] += __shfl_xor_sync(0xffffffffu, shi[mt], 1);
            shi[mt] += __shfl_xor_sync(0xffffffffu, shi[mt], 2);
        }
        if (tg == 0) {
            #pragma unroll
            for (int mt = 0; mt < 2; mt++) {
                spart[(32 * wm + 16 * mt + g) * 4 + wn]     = slo[mt];
                spart[(32 * wm + 16 * mt + g + 8) * 4 + wn] = shi[mt];
            }
        }
        __syncthreads();
        if (t < 64) {
            float s = spart[t * 4] + spart[t * 4 + 1] + spart[t * 4 + 2] + spart[t * 4 + 3];
            srn[t] = 1.f / (sqrtf(s) + 1e-7f);
        }
        __syncthreads();
        #pragma unroll
        for (int mt = 0; mt < 2; mt++) {
            int rl = 32 * wm + 16 * mt + g;
            float rlo = srn[rl], rhi = srn[rl + 8];
            long glo = row0 + rl, ghi = glo + 8;
            #pragma unroll
            for (int nt = 0; nt < 8; nt++) {
                int c = 64 * wn + 8 * nt + 2 * tg;
                *(float2*)(out1 + glo * 256 + c) =
                    make_float2(acc2[mt][nt][0] * rlo, acc2[mt][nt][1] * rlo);
                *(float2*)(out1 + ghi * 256 + c) =
                    make_float2(acc2[mt][nt][2] * rhi, acc2[mt][nt][3] * rhi);
            }
        }
        CP_WAIT0();
        __syncthreads();
    }
}

// ---------------- host launcher: fork/join, MLP undersized grid ----------------
extern "C" void kernel_launch(void* const* d_in, const int* in_sizes, int n_in,
                              void* d_out, int out_size) {
    const float* feat0 = (const float*)d_in[0];
    const float* feat1 = (const float*)d_in[1];
    const float* W1    = (const float*)d_in[2];
    const float* b1    = (const float*)d_in[3];
    const float* gamma = (const float*)d_in[4];
    const float* beta  = (const float*)d_in[5];
    const float* W2    = (const float*)d_in[6];
    const float* b2    = (const float*)d_in[7];
    const float* W3    = (const float*)d_in[8];
    const float* b3    = (const float*)d_in[9];
    const float* W4    = (const float*)d_in[10];
    const float* b4    = (const float*)d_in[11];
    const int* patch_id0 = (const int*)d_in[12];
    const int* patch_id1 = (const int*)d_in[13];
    const int* local_id0 = (const int*)d_in[14];
    const int* local_id1 = (const int*)d_in[15];
    (void)in_sizes; (void)n_in; (void)out_size;

    float* out0 = (float*)d_out;
    float* out1 = out0 + (long)NS0 * O0;

    float*  fr0; cudaGetSymbolAddress((void**)&fr0, g_fr0);
    float*  fr1; cudaGetSymbolAddress((void**)&fr1, g_fr1);
    float*  H;   cudaGetSymbolAddress((void**)&H,   g_H);
    __half* X0h; cudaGetSymbolAddress((void**)&X0h, g_X0h);
    __half* Ahp; cudaGetSymbolAddress((void**)&Ahp, g_Ah);
    __half* W1h; cudaGetSymbolAddress((void**)&W1h, g_W1h);
    __half* W2h; cudaGetSymbolAddress((void**)&W2h, g_W2h);

    cudaFuncSetAttribute(mlp_fp16_kernel, cudaFuncAttributeMaxDynamicSharedMemorySize,
                         MLP_SMEM_BYTES);

    static cudaStream_t s2 = nullptr;
    static cudaEvent_t evFork = nullptr, evJoin = nullptr;
    if (!s2) {
        cudaStreamCreateWithFlags(&s2, cudaStreamNonBlocking);
        cudaEventCreateWithFlags(&evFork, cudaEventDisableTiming);
        cudaEventCreateWithFlags(&evJoin, cudaEventDisableTiming);
    }

    // fork
    cudaEventRecord(evFork, 0);
    cudaStreamWaitEvent(s2, evFork, 0);

    // ---- branch A (default stream): path1 -> persistent MLP ----
    {
        dim3 g1(HW1 / 32, BB);
        transpose_feat1<<<g1, 256>>>(feat1, fr1);
    }
    cvt34<<<160, 512>>>(W3, W4);
    sample1_kernel<<<NS1, 256>>>(patch_id1, local_id1);
    mlp_fp16_kernel<<<MGRID, 256, MLP_SMEM_BYTES>>>(b3, b4, out1);

    // ---- branch B (s2): path0 chain (runs on the 16 free SMs) ----
    {
        dim3 g0(C0 / 32, BB);
        transpose_feat0<<<g0, 256, 0, s2>>>(feat0, fr0);
    }
    cvt12<<<1536, 512, 0, s2>>>(W1, W2);
    sample0_kernel<<<NS0, 256, 0, s2>>>(patch_id0, local_id0);
    {
        dim3 g(H1 / 64, NS0 / 128);
        gemm_fp16<1><<<g, 256, 0, s2>>>(X0h, W1h, b1, H, NS0, H1, C0);
    }
    bnstatsB_kernel<<<4, 256, 0, s2>>>(gamma, beta);
    bnapply_kernel<<<1024, 256, 0, s2>>>();
    {
        dim3 g(O0 / 64, NS0 / 128);
        gemm_fp16<0><<<g, 256, 0, s2>>>(Ahp, W2h, b2, out0, NS0, O0, H1);
    }

    // join
    cudaEventRecord(evJoin, s2);
    cudaStreamWaitEvent(0, evJoin, 0);
}

// round 16
// speedup vs baseline: 1.4777x; 1.4777x over previous
#include <cuda_runtime.h>
#include <cuda_fp16.h>
#include <math.h>
#include <stdint.h>

// ---------------- problem constants ----------------
#define BB   8
#define C0   512
#define HW0  64
#define N0   64
#define L0   8
#define KN0  4
#define C1   64
#define HW1  16384
#define N1   512
#define L1   80
#define KN1  40
#define M1   41
#define NS0  (BB*N0)     // 512
#define NS1  (BB*N1)     // 4096
#define ROWS1 (NS1*M1)   // 167936
#define H1   1024
#define O0   256
#define O1   256
#define NTILES (ROWS1/128)   // 1312
#define MLPGRID 132

// ---------------- scratch ----------------
__device__ float  g_fr0[BB*HW0*C0];
__device__ float  g_fr1[BB*HW1*C1];
__device__ float  g_H [NS0*H1];
__device__ float  g_scale[H1];
__device__ float  g_shift[H1];
__device__ float  g_bnp[2*4*H1];
__device__ __half g_X0h[NS0*C0];
__device__ __half g_Ah [NS0*H1];
__device__ __half g_W1h[H1*C0];
__device__ __half g_W2h[O0*H1];
__device__ __half g_W3h[256*64];
__device__ __half g_W4h[256*256];
__device__ __half g_X1h[(long)ROWS1*C1];

// ---------------- fp16 mma helpers ----------------
__device__ __forceinline__ int reord16(int k) { return ((k & 7) >> 1) * 4 + ((k >> 3) & 1) * 2 + (k & 1); }
__device__ __forceinline__ int reordk(int k)  { return (k & ~15) + reord16(k & 15); }

__device__ __forceinline__ void mma16(float acc[4], uint32_t a0, uint32_t a1,
                                      uint32_t a2, uint32_t a3, uint32_t b0, uint32_t b1) {
    asm volatile(
        "mma.sync.aligned.m16n8k16.row.col.f32.f16.f16.f32 "
        "{%0,%1,%2,%3}, {%4,%5,%6,%7}, {%8,%9}, {%0,%1,%2,%3};"
        : "+f"(acc[0]), "+f"(acc[1]), "+f"(acc[2]), "+f"(acc[3])
        : "r"(a0), "r"(a1), "r"(a2), "r"(a3), "r"(b0), "r"(b1));
}
__device__ __forceinline__ uint32_t pack2(float a, float b) {
    __half2 h = __floats2half2_rn(a, b);
    return *(uint32_t*)&h;
}
__device__ __forceinline__ void cp8(uint32_t dst, const void* src) {
    asm volatile("cp.async.ca.shared.global [%0], [%1], 8;" :: "r"(dst), "l"(src));
}
#define CP_COMMIT() asm volatile("cp.async.commit_group;" ::: "memory")
#define CP_WAIT0()  asm volatile("cp.async.wait_group 0;" ::: "memory")

// ---------------- split weight conversions (per branch) ----------------
__global__ void cvt12(const float* __restrict__ W1, const float* __restrict__ W2) {
    long i = (long)blockIdx.x * blockDim.x + threadIdx.x;   // 786432
    const float* src; __half* dst; long base; int mask;
    if (i < 524288L) { src = W1; dst = g_W1h; base = 0;       mask = 511; }
    else             { src = W2; dst = g_W2h; base = 524288L; mask = 1023; }
    long j = i - base;
    int k = (int)j & mask;
    dst[j - k + reordk(k)] = __float2half_rn(src[j]);
}
__global__ void cvt34(const float* __restrict__ W3, const float* __restrict__ W4) {
    long i = (long)blockIdx.x * blockDim.x + threadIdx.x;   // 81920
    const float* src; __half* dst; long base; int mask;
    if (i < 16384L) { src = W3; dst = g_W3h; base = 0;      mask = 63; }
    else            { src = W4; dst = g_W4h; base = 16384L; mask = 255; }
    long j = i - base;
    int k = (int)j & mask;
    dst[j - k + reordk(k)] = __float2half_rn(src[j]);
}

// ---------------- coalesced transposes ----------------
__global__ void transpose_feat1(const float* __restrict__ f, float* __restrict__ out) {
    __shared__ float sm[64 * 33];
    int b = blockIdx.y;
    int p0 = blockIdx.x * 32;
    int t = threadIdx.x;
    int pp = t & 31, c0 = t >> 5;
    #pragma unroll
    for (int i = 0; i < 8; i++) {
        int c = c0 + i * 8;
        sm[c * 33 + pp] = f[((long)b * 64 + c) * 16384 + p0 + pp];
    }
    __syncthreads();
    #pragma unroll
    for (int i = 0; i < 8; i++) {
        int idx = i * 256 + t;
        int p = idx >> 6, c = idx & 63;
        out[((long)b * 16384 + p0 + p) * 64 + c] = sm[c * 33 + p];
    }
}
__global__ void transpose_feat0(const float* __restrict__ f, float* __restrict__ out) {
    __shared__ float sm[32 * 65];
    int b = blockIdx.y;
    int c0 = blockIdx.x * 32;
    int t = threadIdx.x;
    int p = t & 63, cc = t >> 6;
    #pragma unroll
    for (int i = 0; i < 8; i++) {
        int c = cc + i * 4;
        sm[c * 65 + p] = f[((long)b * 512 + c0 + c) * 64 + p];
    }
    __syncthreads();
    #pragma unroll
    for (int i = 0; i < 8; i++) {
        int idx = i * 256 + t;
        int p2 = idx >> 5, c = idx & 31;
        out[((long)b * 64 + p2) * 512 + c0 + c] = sm[c * 65 + p2];
    }
}

// ---------------- path0 sampling ----------------
__global__ void sample0_kernel(const int* __restrict__ pid, const int* __restrict__ lid) {
    __shared__ float cen[C0];
    __shared__ float sim[L0];
    __shared__ int   rowsS[L0];
    __shared__ int   chosen[KN0];
    int blk = blockIdx.x;
    int b = blk / N0, n = blk % N0;
    int t = threadIdx.x;
    int p = pid[n];
    const float* base = g_fr0 + (long)b * HW0 * C0;
    const float* cptr = base + (long)p * C0;
    for (int c = t; c < C0; c += 256) cen[c] = cptr[c];
    if (t < L0) rowsS[t] = lid[n * L0 + t];
    __syncthreads();
    int w = t >> 5, lane = t & 31;
    {
        const float* lp = base + (long)rowsS[w] * C0;
        float dot = 0.f, ss = 0.f;
        for (int c = lane; c < C0; c += 32) {
            float v = lp[c];
            dot += v * cen[c];
            ss  += v * v;
        }
        for (int o = 16; o > 0; o >>= 1) {
            dot += __shfl_down_sync(0xffffffffu, dot, o);
            ss  += __shfl_down_sync(0xffffffffu, ss,  o);
        }
        if (lane == 0) sim[w] = dot / fmaxf(sqrtf(ss), 1e-12f);
    }
    __syncthreads();
    if (t < L0) {
        int l = t;
        float v = sim[l];
        int cnt = 0;
        #pragma unroll
        for (int j = 0; j < L0; j++) {
            float u = sim[j];
            cnt += (u > v || (u == v && j < l)) ? 1 : 0;
        }
        if (cnt < KN0) chosen[cnt] = rowsS[l];
    }
    __syncthreads();
    for (int c = t; c < C0; c += 256) {
        float acc = cen[c];
        #pragma unroll
        for (int r = 0; r < KN0; r++) acc += base[(long)chosen[r] * C0 + c];
        g_X0h[(long)blk * C0 + reordk(c)] = __float2half_rn(acc * 0.2f);
    }
}

// ---------------- path1 sampling (256 threads, packed stores) ----------------
__global__ void sample1_kernel(const int* __restrict__ pid, const int* __restrict__ lid) {
    __shared__ float cen[C1];
    __shared__ float loc[L1 * 68];
    __shared__ float sim[L1];
    __shared__ int   rowsS[L1];
    __shared__ int   sel[KN1];
    int blk = blockIdx.x;
    int b = blk / N1, n = blk % N1;
    int t = threadIdx.x;
    const float* base = g_fr1 + (long)b * HW1 * C1;
    int p = pid[n];
    if (t < C1) cen[t] = base[(long)p * C1 + t];
    if (t < L1) rowsS[t] = lid[n * L1 + t];
    __syncthreads();
    #pragma unroll
    for (int i = t; i < L1 * 16; i += 256) {
        int l = i >> 4, c4 = i & 15;
        float4 v = *(const float4*)(base + (long)rowsS[l] * C1 + c4 * 4);
        *(float4*)(loc + l * 68 + c4 * 4) = v;
    }
    __syncthreads();
    if (t < L1) {
        const float4* lp = (const float4*)(loc + t * 68);
        const float4* cp = (const float4*)cen;
        float dot = 0.f, ss = 0.f;
        #pragma unroll
        for (int c4 = 0; c4 < 16; c4++) {
            float4 v = lp[c4], cv = cp[c4];
            dot += v.x * cv.x + v.y * cv.y + v.z * cv.z + v.w * cv.w;
            ss  += v.x * v.x + v.y * v.y + v.z * v.z + v.w * v.w;
        }
        sim[t] = dot / fmaxf(sqrtf(ss), 1e-12f);
    }
    __syncthreads();
    if (t < L1) {
        int l = t;
        float v = sim[l];
        int cnt = 0;
        #pragma unroll
        for (int j = 0; j < L1; j++) {
            float u = sim[j];
            cnt += (u > v || (u == v && j < l)) ? 1 : 0;
        }
        if (cnt < KN1) sel[cnt] = l;
    }
    __syncthreads();
    uint2* outp = (uint2*)(g_X1h + (long)blk * M1 * C1);
    #pragma unroll
    for (int i = t; i < M1 * 16; i += 256) {
        int m = i >> 4, q = i & 15;
        int b16 = q >> 2, tq = q & 3;
        int c0 = 16 * b16 + 2 * tq;
        const float* srcp = (m == 0) ? cen : (loc + sel[m - 1] * 68);
        uint2 o;
        o.x = pack2(srcp[c0], srcp[c0 + 1]);
        o.y = pack2(srcp[c0 + 8], srcp[c0 + 9]);
        outp[m * 16 + q] = o;
    }
}

// ---------------- fp16 mma GEMM (path0); optional BN-partial epilogue ----------------
template<int BNSTATS>
__global__ __launch_bounds__(256) void gemm_fp16(const __half* __restrict__ Ah,
                                                 const __half* __restrict__ Bh,
                                                 const float* __restrict__ bias,
                                                 float* __restrict__ C,
                                                 int M, int N, int K) {
    __shared__ __half sA[128 * 48];
    __shared__ __half sB[64 * 48];
    int t = threadIdx.x;
    int w = t >> 5, lane = t & 31;
    int g = lane >> 2, tg = lane & 3;
    int rw0 = w * 16;
    int m0 = blockIdx.y * 128, n0 = blockIdx.x * 64;

    float acc[8][4];
    #pragma unroll
    for (int nt = 0; nt < 8; nt++)
        #pragma unroll
        for (int q = 0; q < 4; q++) acc[nt][q] = 0.f;

    for (int kc = 0; kc < K / 32; kc++) {
        __syncthreads();
        #pragma unroll
        for (int i = 0; i < 2; i++) {
            int idx = i * 256 + t;
            int r = idx >> 2, q = idx & 3;
            *(uint4*)(sA + r * 48 + q * 8) =
                *(const uint4*)(Ah + (long)(m0 + r) * K + kc * 32 + q * 8);
        }
        {
            int r = t >> 2, q = t & 3;
            *(uint4*)(sB + r * 48 + q * 8) =
                *(const uint4*)(Bh + (long)(n0 + r) * K + kc * 32 + q * 8);
        }
        __syncthreads();
        #pragma unroll
        for (int ks = 0; ks < 2; ks++) {
            uint2 alo = *(const uint2*)(sA + (rw0 + g) * 48 + ks * 16 + 4 * tg);
            uint2 ahi = *(const uint2*)(sA + (rw0 + g + 8) * 48 + ks * 16 + 4 * tg);
            #pragma unroll
            for (int nt = 0; nt < 8; nt++) {
                uint2 bb = *(const uint2*)(sB + (nt * 8 + g) * 48 + ks * 16 + 4 * tg);
                mma16(acc[nt], alo.x, ahi.x, alo.y, ahi.y, bb.x, bb.y);
            }
        }
    }
    __shared__ float red[2][8][64];
    #pragma unroll
    for (int nt = 0; nt < 8; nt++) {
        int col = n0 + nt * 8 + 2 * tg;
        float bj0 = bias[col], bj1 = bias[col + 1];
        float y00 = acc[nt][0] + bj0, y01 = acc[nt][1] + bj1;
        float y10 = acc[nt][2] + bj0, y11 = acc[nt][3] + bj1;
        C[(long)(m0 + rw0 + g    ) * N + col    ] = y00;
        C[(long)(m0 + rw0 + g    ) * N + col + 1] = y01;
        C[(long)(m0 + rw0 + g + 8) * N + col    ] = y10;
        C[(long)(m0 + rw0 + g + 8) * N + col + 1] = y11;
        if (BNSTATS) {
            float s0 = y00 + y10, q0 = y00 * y00 + y10 * y10;
            float s1 = y01 + y11, q1 = y01 * y01 + y11 * y11;
            #pragma unroll
            for (int o = 16; o >= 4; o >>= 1) {
                s0 += __shfl_down_sync(0xffffffffu, s0, o);
                q0 += __shfl_down_sync(0xffffffffu, q0, o);
                s1 += __shfl_down_sync(0xffffffffu, s1, o);
                q1 += __shfl_down_sync(0xffffffffu, q1, o);
            }
            if (g == 0) {
                red[0][w][nt * 8 + 2 * tg]     = s0;
                red[0][w][nt * 8 + 2 * tg + 1] = s1;
                red[1][w][nt * 8 + 2 * tg]     = q0;
                red[1][w][nt * 8 + 2 * tg + 1] = q1;
            }
        }
    }
    if (BNSTATS) {
        __syncthreads();
        if (t < 64) {
            float s = 0.f, q = 0.f;
            #pragma unroll
            for (int ww = 0; ww < 8; ww++) { s += red[0][ww][t]; q += red[1][ww][t]; }
            g_bnp[blockIdx.y * H1 + n0 + t] = s;
            g_bnp[4 * H1 + blockIdx.y * H1 + n0 + t] = q;
        }
    }
}

// ---------------- BN finish ----------------
__global__ void bnstatsB_kernel(const float* __restrict__ gamma, const float* __restrict__ beta) {
    int j = blockIdx.x * 256 + threadIdx.x;
    float s = 0.f, ss = 0.f;
    #pragma unroll
    for (int b = 0; b < 4; b++) {
        s  += g_bnp[b * H1 + j];
        ss += g_bnp[4 * H1 + b * H1 + j];
    }
    float mu  = s / NS0;
    float var = ss / NS0 - mu * mu;
    float sc  = gamma[j] / sqrtf(var + 1e-5f);
    g_scale[j] = sc;
    g_shift[j] = beta[j] - mu * sc;
}
__global__ void bnapply_kernel() {
    long total = (long)NS0 * H1;
    for (long i = (long)blockIdx.x * blockDim.x + threadIdx.x; i < total;
         i += (long)gridDim.x * blockDim.x) {
        int j = (int)(i % H1);
        float v = g_H[i] * g_scale[j] + g_shift[j];
        g_Ah[i - j + reordk(j)] = __float2half_rn(fmaxf(v, 0.f));
    }
}

// ================= path1 MLP: persistent, fragment-major, 256 threads, 64x64 =====
#define XF_OFF   0u
#define W4F_OFF  16384u
#define HF_OFF   147456u
#define FB_OFF   212992u
#define MLP_SMEM_BYTES (212992 + 1152*4)

__global__ __launch_bounds__(256, 1) void mlp_fp16_kernel(const float* __restrict__ b3,
                                                          const float* __restrict__ b4,
                                                          float* __restrict__ out1) {
    extern __shared__ char sm[];
    float* sb3   = (float*)(sm + FB_OFF);
    float* sb4   = sb3 + 256;
    float* spart = sb4 + 256;
    float* srn   = spart + 512;

    int t = threadIdx.x;
    int lane = t & 31;
    int g = lane >> 2, tg = lane & 3;
    int w = t >> 5;
    int wm = w >> 2;
    int wn = w & 3;
    int bid = blockIdx.x;

    uint32_t sbase = (uint32_t)__cvta_generic_to_shared(sm);

    #pragma unroll 8
    for (int i = t; i < 16384; i += 256) {
        int f = i >> 5, l = i & 31;
        int ntg = f >> 4, ck = f & 15, gg = l >> 2, tt = l & 3;
        cp8(sbase + W4F_OFF + (uint32_t)i * 8u,
            g_W4h + (8 * ntg + gg) * 256 + 16 * ck + 4 * tt);
    }
    {
        long tile0 = bid;
        #pragma unroll 8
        for (int i = t; i < 2048; i += 256) {
            int f = i >> 6, rest = i & 63;
            int l = rest >> 1, h = rest & 1;
            int mb = f >> 2, ks = f & 3, gg = l >> 2, tt = l & 3;
            cp8(sbase + XF_OFF + (uint32_t)(f * 512 + l * 16 + h * 8),
                g_X1h + (tile0 * 128 + 16 * mb + gg + 8 * h) * 64 + 16 * ks + 4 * tt);
        }
    }
    CP_COMMIT();

    sb3[t] = b3[t];
    sb4[t] = b4[t];

    uint2 w3r[8][4];
    #pragma unroll
    for (int nt = 0; nt < 8; nt++)
        #pragma unroll
        for (int ks = 0; ks < 4; ks++)
            w3r[nt][ks] = *(const uint2*)(g_W3h + (64 * wn + 8 * nt + g) * 64 + 16 * ks + 4 * tg);

    CP_WAIT0();
    __syncthreads();

    for (long tile = bid; tile < NTILES; tile += MLPGRID) {
        long row0 = tile * 128;

        float acc1[4][8][4];
        #pragma unroll
        for (int mt = 0; mt < 4; mt++)
            #pragma unroll
            for (int nt = 0; nt < 8; nt++)
                #pragma unroll
                for (int q = 0; q < 4; q++) acc1[mt][nt][q] = 0.f;

        #pragma unroll
        for (int ks = 0; ks < 4; ks++) {
            uint4 ax[4];
            #pragma unroll
            for (int mt = 0; mt < 4; mt++)
                ax[mt] = *(const uint4*)(sm + XF_OFF + ((4 * wm + mt) * 4 + ks) * 512 + lane * 16);
            #pragma unroll
            for (int nt = 0; nt < 8; nt++) {
                uint2 bb = w3r[nt][ks];
                #pragma unroll
                for (int mt = 0; mt < 4; mt++)
                    mma16(acc1[mt][nt], ax[mt].x, ax[mt].z, ax[mt].y, ax[mt].w, bb.x, bb.y);
            }
        }
        #pragma unroll
        for (int mt = 0; mt < 4; mt++)
            #pragma unroll
            for (int nt = 0; nt < 8; nt++) {
                int c = 64 * wn + 8 * nt + 2 * tg;
                float bb0 = sb3[c], bb1 = sb3[c + 1];
                uint2 v;
                v.x = pack2(fmaxf(acc1[mt][nt][0] + bb0, 0.f), fmaxf(acc1[mt][nt][1] + bb1, 0.f));
                v.y = pack2(fmaxf(acc1[mt][nt][2] + bb0, 0.f), fmaxf(acc1[mt][nt][3] + bb1, 0.f));
                int mb = 4 * wm + mt;
                int ck = 4 * wn + (nt >> 1);
                *(uint2*)(sm + HF_OFF + (mb * 16 + ck) * 512 + lane * 16 + (nt & 1) * 8) = v;
            }
        __syncthreads();

        {
            long tn = tile + MLPGRID;
            if (tn < NTILES) {
                #pragma unroll 8
                for (int i = t; i < 2048; i += 256) {
                    int f = i >> 6, rest = i & 63;
                    int l = rest >> 1, h = rest & 1;
                    int mb = f >> 2, ks = f & 3, gg = l >> 2, tt = l & 3;
                    cp8(sbase + XF_OFF + (uint32_t)(f * 512 + l * 16 + h * 8),
                        g_X1h + (tn * 128 + 16 * mb + gg + 8 * h) * 64 + 16 * ks + 4 * tt);
                }
            }
            CP_COMMIT();
        }

        float acc2[4][8][4];
        #pragma unroll
        for (int mt = 0; mt < 4; mt++)
            #pragma unroll
            for (int nt = 0; nt < 8; nt++)
                #pragma unroll
                for (int q = 0; q < 4; q++) acc2[mt][nt][q] = 0.f;

        #pragma unroll 4
        for (int ck = 0; ck < 16; ck++) {
            uint4 ha[4];
            #pragma unroll
            for (int mt = 0; mt < 4; mt++)
                ha[mt] = *(const uint4*)(sm + HF_OFF + ((4 * wm + mt) * 16 + ck) * 512 + lane * 16);
            uint2 wb[8];
            #pragma unroll
            for (int nt = 0; nt < 8; nt++)
                wb[nt] = *(const uint2*)(sm + W4F_OFF + ((8 * wn + nt) * 16 + ck) * 256 + lane * 8);
            #pragma unroll
            for (int nt = 0; nt < 8; nt++)
                #pragma unroll
                for (int mt = 0; mt < 4; mt++)
                    mma16(acc2[mt][nt], ha[mt].x, ha[mt].y, ha[mt].z, ha[mt].w,
                          wb[nt].x, wb[nt].y);
        }

        float slo[4] = {0.f, 0.f, 0.f, 0.f}, shi[4] = {0.f, 0.f, 0.f, 0.f};
        #pragma unroll
        for (int mt = 0; mt < 4; mt++)
            #pragma unroll
            for (int nt = 0; nt < 8; nt++) {
                int c = 64 * wn + 8 * nt + 2 * tg;
                float bb0 = sb4[c], bb1 = sb4[c + 1];
                acc2[mt][nt][0] += bb0; acc2[mt][nt][1] += bb1;
                acc2[mt][nt][2] += bb0; acc2[mt][nt][3] += bb1;
                slo[mt] += acc2[mt][nt][0] * acc2[mt][nt][0] + acc2[mt][nt][1] * acc2[mt][nt][1];
                shi[mt] += acc2[mt][nt][2] * acc2[mt][nt][2] + acc2[mt][nt][3] * acc2[mt][nt][3];
            }
        #pragma unroll
        for (int mt = 0; mt < 4; mt++) {
            slo[mt] += __shfl_xor_sync(0xffffffffu, slo[mt], 1);
            slo[mt] += __shfl_xor_sync(0xffffffffu, slo[mt], 2);
            shi[mt] += __shfl_xor_sync(0xffffffffu, shi[mt], 1);
            shi[mt] += __shfl_xor_sync(0xffffffffu, shi[mt], 2);
        }
        if (tg == 0) {
            #pragma unroll
            for (int mt = 0; mt < 4; mt++) {
                spart[(64 * wm + 16 * mt + g) * 4 + wn]     = slo[mt];
                spart[(64 * wm + 16 * mt + g + 8) * 4 + wn] = shi[mt];
            }
        }
        __syncthreads();
        if (t < 128) {
            float s = spart[t * 4] + spart[t * 4 + 1] + spart[t * 4 + 2] + spart[t * 4 + 3];
            srn[t] = 1.f / (sqrtf(s) + 1e-7f);
        }
        __syncthreads();
        #pragma unroll
        for (int mt = 0; mt < 4; mt++) {
            int rl = 64 * wm + 16 * mt + g;
            float rlo = srn[rl], rhi = srn[rl + 8];
            long glo = row0 + rl, ghi = glo + 8;
            #pragma unroll
            for (int nt = 0; nt < 8; nt++) {
                int c = 64 * wn + 8 * nt + 2 * tg;
                *(float2*)(out1 + glo * 256 + c) =
                    make_float2(acc2[mt][nt][0] * rlo, acc2[mt][nt][1] * rlo);
                *(float2*)(out1 + ghi * 256 + c) =
                    make_float2(acc2[mt][nt][2] * rhi, acc2[mt][nt][3] * rhi);
            }
        }
        CP_WAIT0();
        __syncthreads();
    }
}

// ---------------- host launcher: fork/join with undersized MLP grid ----------------
extern "C" void kernel_launch(void* const* d_in, const int* in_sizes, int n_in,
                              void* d_out, int out_size) {
    const float* feat0 = (const float*)d_in[0];
    const float* feat1 = (const float*)d_in[1];
    const float* W1    = (const float*)d_in[2];
    const float* b1    = (const float*)d_in[3];
    const float* gamma = (const float*)d_in[4];
    const float* beta  = (const float*)d_in[5];
    const float* W2    = (const float*)d_in[6];
    const float* b2    = (const float*)d_in[7];
    const float* W3    = (const float*)d_in[8];
    const float* b3    = (const float*)d_in[9];
    const float* W4    = (const float*)d_in[10];
    const float* b4    = (const float*)d_in[11];
    const int* patch_id0 = (const int*)d_in[12];
    const int* patch_id1 = (const int*)d_in[13];
    const int* local_id0 = (const int*)d_in[14];
    const int* local_id1 = (const int*)d_in[15];
    (void)in_sizes; (void)n_in; (void)out_size;

    float* out0 = (float*)d_out;
    float* out1 = out0 + (long)NS0 * O0;

    float*  fr0; cudaGetSymbolAddress((void**)&fr0, g_fr0);
    float*  fr1; cudaGetSymbolAddress((void**)&fr1, g_fr1);
    float*  H;   cudaGetSymbolAddress((void**)&H,   g_H);
    __half* X0h; cudaGetSymbolAddress((void**)&X0h, g_X0h);
    __half* Ahp; cudaGetSymbolAddress((void**)&Ahp, g_Ah);
    __half* W1h; cudaGetSymbolAddress((void**)&W1h, g_W1h);
    __half* W2h; cudaGetSymbolAddress((void**)&W2h, g_W2h);

    cudaFuncSetAttribute(mlp_fp16_kernel, cudaFuncAttributeMaxDynamicSharedMemorySize,
                         MLP_SMEM_BYTES);

    static cudaStream_t s2 = nullptr;
    static cudaEvent_t evFork = nullptr, evJoin = nullptr;
    if (!s2) {
        cudaStreamCreateWithFlags(&s2, cudaStreamNonBlocking);
        cudaEventCreateWithFlags(&evFork, cudaEventDisableTiming);
        cudaEventCreateWithFlags(&evJoin, cudaEventDisableTiming);
    }

    // fork
    cudaEventRecord(evFork, 0);
    cudaStreamWaitEvent(s2, evFork, 0);

    // ---- branch A (default stream): path1 -> persistent MLP at 132 CTAs ----
    {
        dim3 g1(HW1 / 32, BB);
        transpose_feat1<<<g1, 256>>>(feat1, fr1);
    }
    cvt34<<<160, 512>>>(W3, W4);
    sample1_kernel<<<NS1, 256>>>(patch_id1, local_id1);
    mlp_fp16_kernel<<<MLPGRID, 256, MLP_SMEM_BYTES>>>(b3, b4, out1);

    // ---- branch B (s2): path0 chain (fills the 16 free SMs) ----
    {
        dim3 g0(C0 / 32, BB);
        transpose_feat0<<<g0, 256, 0, s2>>>(feat0, fr0);
    }
    cvt12<<<1536, 512, 0, s2>>>(W1, W2);
    sample0_kernel<<<NS0, 256, 0, s2>>>(patch_id0, local_id0);
    {
        dim3 g(H1 / 64, NS0 / 128);
        gemm_fp16<1><<<g, 256, 0, s2>>>(X0h, W1h, b1, H, NS0, H1, C0);
    }
    bnstatsB_kernel<<<4, 256, 0, s2>>>(gamma, beta);
    bnapply_kernel<<<1024, 256, 0, s2>>>();
    {
        dim3 g(O0 / 64, NS0 / 128);
        gemm_fp16<0><<<g, 256, 0, s2>>>(Ahp, W2h, b2, out0, NS0, O0, H1);
    }

    // join
    cudaEventRecord(evJoin, s2);
    cudaStreamWaitEvent(0, evJoin, 0);
}